// round 4
// baseline (speedup 1.0000x reference)
#include <cuda_runtime.h>
#include <math.h>

#define HD 64
#define MAXN 100000
#define MAXG 512
#define CAP 80            // max in-degree bucket capacity (Poisson(16) tail ~1e-30)

// ---- scratch (device globals; no allocation allowed) ----
// 128B alignment: accessed with 128-bit vector loads/stores/REDs.
__device__ __align__(128) float  g_h [MAXN * HD];
__device__ __align__(128) float  g_h2[MAXN * HD];
__device__ __align__(128) float  g_t [MAXN * HD];
__device__ __align__(128) float  g_dinv[MAXN];
__device__ __align__(128) float  g_pool[MAXG * HD];
__device__ __align__(128) float  g_cnt [MAXG];
__device__ __align__(128) int    g_fill[MAXN];                 // in-degree / fill counter
__device__ __align__(128) float2 g_bucket[(size_t)MAXN * CAP]; // {bits(src), nrm}
__device__ int g_is64;

__device__ __forceinline__ void red_v4(float* p, float4 v) {
    asm volatile("red.global.add.v4.f32 [%0], {%1,%2,%3,%4};"
                 :: "l"(p), "f"(v.x), "f"(v.y), "f"(v.z), "f"(v.w) : "memory");
}

// ---------------------------------------------------------------------------
// index dtype detection: values in [0, 100000). If int64, every odd 32-bit
// word is zero; 128 consecutive zero-words are impossible for int32 indices.
// ---------------------------------------------------------------------------
__global__ void k_detect(const int* __restrict__ ei) {
    if (threadIdx.x == 0 && blockIdx.x == 0) {
        int allz = 1, anynz = 0;
        for (int i = 0; i < 256; i += 2) {
            if (ei[i + 1] != 0) allz = 0;
            if (ei[i]     != 0) anynz = 1;
        }
        g_is64 = (allz && anynz) ? 1 : 0;
    }
}

__global__ void k_init(int n, int g) {
    int i = blockIdx.x * blockDim.x + threadIdx.x;
    if (i < n) { g_dinv[i] = 1.0f; g_fill[i] = 0; }   // deg starts at 1 (self loop)
    if (i < g * HD) g_pool[i] = 0.0f;
    if (i < g)      g_cnt[i]  = 0.0f;
}

__global__ void k_deg(const void* __restrict__ ei, int E) {
    int is64 = g_is64;
    int i = blockIdx.x * blockDim.x + threadIdx.x;
    if (i < E) {
        int d = is64 ? (int)((const long long*)ei)[(long long)E + i]
                     : ((const int*)ei)[E + i];
        atomicAdd(&g_dinv[d], 1.0f);
    }
}

__global__ void k_dinv(int n) {
    int i = blockIdx.x * blockDim.x + threadIdx.x;
    if (i < n) g_dinv[i] = rsqrtf(g_dinv[i]);   // deg >= 1 always
}

// place each edge into its destination bucket: {src, dinv[s]*dinv[d]}
__global__ void k_place(const void* __restrict__ ei, int E) {
    int is64 = g_is64;
    int e = blockIdx.x * blockDim.x + threadIdx.x;
    if (e < E) {
        int s, d;
        if (is64) {
            s = (int)((const long long*)ei)[e];
            d = (int)((const long long*)ei)[(long long)E + e];
        } else {
            s = ((const int*)ei)[e];
            d = ((const int*)ei)[E + e];
        }
        float nrm = g_dinv[s] * g_dinv[d];
        int slot = atomicAdd(&g_fill[d], 1);
        if (slot < CAP)
            g_bucket[(size_t)d * CAP + slot] = make_float2(__int_as_float(s), nrm);
    }
}

// ---------------------------------------------------------------------------
// Row GEMM: out[r,:] = (RELU? relu(A[r,:]) : A[r,:]) @ W  (+ bias if given)
// If SELF: also write out2[r,:] = bias2 + out[r,:] * dinv[r]^2 (fused selfinit)
// W is [K,64] row-major. Thread-per-row; W chunk in smem (uniform broadcast
// LDS.128); A tile staged in smem with pad-33 (conflict-free).
// ---------------------------------------------------------------------------
template<int K, bool RELU, bool SELF>
__global__ __launch_bounds__(256)
void k_gemm(const float* __restrict__ A, int n,
            const float* __restrict__ W, const float* __restrict__ bias,
            float* __restrict__ out,
            const float* __restrict__ bias2, float* __restrict__ out2) {
    __shared__ float ws[32 * 64];     // current K-chunk of W
    __shared__ float as[256 * 33];    // A tile, padded
    const int tid = threadIdx.x;
    const int r0  = blockIdx.x * 256;
    const int r   = r0 + tid;

    float4 acc[16];
    #pragma unroll
    for (int j = 0; j < 16; j++) acc[j] = make_float4(0.f, 0.f, 0.f, 0.f);

    for (int kc = 0; kc < K; kc += 32) {
        __syncthreads();
        #pragma unroll
        for (int i = tid; i < 512; i += 256)
            ((float4*)ws)[i] = ((const float4*)W)[kc * 16 + i];
        #pragma unroll
        for (int q = 0; q < 8; q++) {
            int f   = tid + 256 * q;
            int row = f >> 3, c4 = f & 7;
            int gr  = r0 + row;
            float4 v = make_float4(0.f, 0.f, 0.f, 0.f);
            if (gr < n)
                v = *(const float4*)(A + (size_t)gr * K + kc + c4 * 4);
            if (RELU) {
                v.x = fmaxf(v.x, 0.f); v.y = fmaxf(v.y, 0.f);
                v.z = fmaxf(v.z, 0.f); v.w = fmaxf(v.w, 0.f);
            }
            float* dst = &as[row * 33 + c4 * 4];
            dst[0] = v.x; dst[1] = v.y; dst[2] = v.z; dst[3] = v.w;
        }
        __syncthreads();
        #pragma unroll 8
        for (int k = 0; k < 32; k++) {
            float a = as[tid * 33 + k];
            const float4* w4 = (const float4*)(ws + k * 64);
            #pragma unroll
            for (int j = 0; j < 16; j++) {
                float4 w = w4[j];
                acc[j].x += a * w.x; acc[j].y += a * w.y;
                acc[j].z += a * w.z; acc[j].w += a * w.w;
            }
        }
    }
    if (r < n) {
        float4* o = (float4*)(out + (size_t)r * HD);
        if (bias) {
            #pragma unroll
            for (int j = 0; j < 16; j++) {
                float4 b = ((const float4*)bias)[j];
                acc[j].x += b.x; acc[j].y += b.y; acc[j].z += b.z; acc[j].w += b.w;
            }
        }
        #pragma unroll
        for (int j = 0; j < 16; j++) o[j] = acc[j];
        if (SELF) {
            float di = g_dinv[r];
            float s  = di * di;
            float4* o2 = (float4*)(out2 + (size_t)r * HD);
            #pragma unroll
            for (int j = 0; j < 16; j++) {
                float4 b = ((const float4*)bias2)[j];
                float4 v;
                v.x = b.x + acc[j].x * s; v.y = b.y + acc[j].y * s;
                v.z = b.z + acc[j].z * s; v.w = b.w + acc[j].w * s;
                o2[j] = v;
            }
        }
    }
}

// ---------------------------------------------------------------------------
// Edge embed: e = edge_attr @ W_edge + b_edge ; h[src] += e  (vector RED)
// ---------------------------------------------------------------------------
__global__ __launch_bounds__(256)
void k_edge_embed(const float* __restrict__ EA, int E,
                  const float* __restrict__ W, const float* __restrict__ bias,
                  const void* __restrict__ ei, float* __restrict__ h) {
    __shared__ float ws[32 * 64];
    __shared__ float as[256 * 33];
    const int tid = threadIdx.x;
    const int r0  = blockIdx.x * 256;
    const int r   = r0 + tid;
    const int is64 = g_is64;

    #pragma unroll
    for (int i = tid; i < 512; i += 256)
        ((float4*)ws)[i] = ((const float4*)W)[i];

    #pragma unroll
    for (int q = 0; q < 8; q++) {
        int f   = tid + 256 * q;
        int row = f >> 3, c4 = f & 7;
        int gr  = r0 + row;
        float4 v = make_float4(0.f, 0.f, 0.f, 0.f);
        if (gr < E)
            v = *(const float4*)(EA + (size_t)gr * 32 + c4 * 4);
        float* dst = &as[row * 33 + c4 * 4];
        dst[0] = v.x; dst[1] = v.y; dst[2] = v.z; dst[3] = v.w;
    }
    __syncthreads();

    float4 acc[16];
    #pragma unroll
    for (int j = 0; j < 16; j++) acc[j] = make_float4(0.f, 0.f, 0.f, 0.f);
    #pragma unroll 8
    for (int k = 0; k < 32; k++) {
        float a = as[tid * 33 + k];
        const float4* w4 = (const float4*)(ws + k * 64);
        #pragma unroll
        for (int j = 0; j < 16; j++) {
            float4 w = w4[j];
            acc[j].x += a * w.x; acc[j].y += a * w.y;
            acc[j].z += a * w.z; acc[j].w += a * w.w;
        }
    }
    if (r < E) {
        int s = is64 ? (int)((const long long*)ei)[r] : ((const int*)ei)[r];
        float* hp = h + (size_t)s * HD;
        #pragma unroll
        for (int j = 0; j < 16; j++) {
            float4 b = ((const float4*)bias)[j];
            float4 v;
            v.x = acc[j].x + b.x; v.y = acc[j].y + b.y;
            v.z = acc[j].z + b.z; v.w = acc[j].w + b.w;
            red_v4(hp + j * 4, v);
        }
    }
}

// ---------------------------------------------------------------------------
// Gather aggregation: warp per node; out[n] (pre-seeded with bias + self term)
// += sum over in-edges of t[src] * nrm. No atomics — warp owns the row.
// ---------------------------------------------------------------------------
__global__ __launch_bounds__(256)
void k_gather(const float* __restrict__ t, float* __restrict__ out, int N) {
    int warp = (blockIdx.x * blockDim.x + threadIdx.x) >> 5;
    int lane = threadIdx.x & 31;
    if (warp >= N) return;
    int deg = g_fill[warp];
    if (deg > CAP) deg = CAP;
    const float2* bk = &g_bucket[(size_t)warp * CAP];
    float* op = out + (size_t)warp * HD;
    float a0 = op[lane], a1 = op[lane + 32];
    int i = 0;
    for (; i + 2 <= deg; i += 2) {           // 2-way unroll for MLP
        float2 r0 = bk[i], r1 = bk[i + 1];
        int s0 = __float_as_int(r0.x), s1 = __float_as_int(r1.x);
        const float* t0 = t + (size_t)s0 * HD;
        const float* t1 = t + (size_t)s1 * HD;
        float v00 = t0[lane], v01 = t0[lane + 32];
        float v10 = t1[lane], v11 = t1[lane + 32];
        a0 += v00 * r0.y + v10 * r1.y;
        a1 += v01 * r0.y + v11 * r1.y;
    }
    if (i < deg) {
        float2 r = bk[i];
        const float* ts = t + (size_t)__float_as_int(r.x) * HD;
        a0 += ts[lane] * r.y;
        a1 += ts[lane + 32] * r.y;
    }
    op[lane] = a0; op[lane + 32] = a1;
}

// sorted-batch mean-pool: warp handles a contiguous node chunk, accumulates in
// regs while graph id unchanged, flushes on boundary.
__global__ void k_pool(const void* __restrict__ batch,
                       const float* __restrict__ h, int N) {
    const int is64 = g_is64;
    const int lane = threadIdx.x & 31;
    int warp = (blockIdx.x * blockDim.x + threadIdx.x) >> 5;
    int nw   = (gridDim.x * blockDim.x) >> 5;
    int chunk = (N + nw - 1) / nw;
    int n0 = warp * chunk;
    int n1 = min(N, n0 + chunk);
    float a0 = 0.f, a1 = 0.f, c = 0.f;
    int cur = -1;
    for (int n = n0; n < n1; n++) {
        int b = is64 ? (int)((const long long*)batch)[n] : ((const int*)batch)[n];
        if (b != cur) {
            if (cur >= 0) {
                atomicAdd(&g_pool[cur * HD + lane],      a0);
                atomicAdd(&g_pool[cur * HD + 32 + lane], a1);
                if (lane == 0) atomicAdd(&g_cnt[cur], c);
            }
            cur = b; a0 = a1 = 0.f; c = 0.f;
        }
        a0 += h[(size_t)n * HD + lane];
        a1 += h[(size_t)n * HD + 32 + lane];
        c  += 1.0f;
    }
    if (cur >= 0) {
        atomicAdd(&g_pool[cur * HD + lane],      a0);
        atomicAdd(&g_pool[cur * HD + 32 + lane], a1);
        if (lane == 0) atomicAdd(&g_cnt[cur], c);
    }
}

// warp-per-graph classifier: relu(mean @ Wc1 + bc1) @ Wc2 + bc2
__global__ void k_classify(const float* __restrict__ Wc1, const float* __restrict__ bc1,
                           const float* __restrict__ Wc2, const float* __restrict__ bc2,
                           float* __restrict__ out, int G) {
    int warp = (blockIdx.x * blockDim.x + threadIdx.x) >> 5;
    int lane = threadIdx.x & 31;
    if (warp >= G) return;
    float inv = 1.0f / fmaxf(g_cnt[warp], 1.0f);
    float c1 = bc1[lane];
    #pragma unroll 8
    for (int k = 0; k < HD; k++) {
        float m = g_pool[warp * HD + k] * inv;
        c1 += m * Wc1[k * 32 + lane];
    }
    c1 = fmaxf(c1, 0.f);
    float v = c1 * Wc2[lane];
    #pragma unroll
    for (int off = 16; off; off >>= 1)
        v += __shfl_down_sync(0xffffffffu, v, off);
    if (lane == 0) out[warp] = v + bc2[0];
}

static inline int cdiv(int a, int b) { return (a + b - 1) / b; }

extern "C" void kernel_launch(void* const* d_in, const int* in_sizes, int n_in,
                              void* d_out, int out_size) {
    const float* x     = (const float*)d_in[0];
    const void*  ei    = d_in[1];
    const float* ea    = (const float*)d_in[2];
    const void*  batch = d_in[3];
    const float* Wn  = (const float*)d_in[4];  const float* bn  = (const float*)d_in[5];
    const float* We  = (const float*)d_in[6];  const float* be  = (const float*)d_in[7];
    const float* W1  = (const float*)d_in[8];  const float* b1  = (const float*)d_in[9];
    const float* W2  = (const float*)d_in[10]; const float* b2  = (const float*)d_in[11];
    const float* W3  = (const float*)d_in[12]; const float* b3  = (const float*)d_in[13];
    const float* Wc1 = (const float*)d_in[14]; const float* bc1 = (const float*)d_in[15];
    const float* Wc2 = (const float*)d_in[16]; const float* bc2 = (const float*)d_in[17];
    float* out = (float*)d_out;

    const int N = in_sizes[3];        // batch has N elements
    const int E = in_sizes[2] / 32;   // edge_attr is [E,32]
    const int G = out_size;

    float *ph, *ph2, *pt;
    cudaGetSymbolAddress((void**)&ph,  g_h);
    cudaGetSymbolAddress((void**)&ph2, g_h2);
    cudaGetSymbolAddress((void**)&pt,  g_t);

    k_detect<<<1, 32>>>((const int*)ei);
    int initN = N > G * HD ? N : G * HD;
    k_init<<<cdiv(initN, 256), 256>>>(N, G);
    k_deg  <<<cdiv(E, 256), 256>>>(ei, E);
    k_dinv <<<cdiv(N, 256), 256>>>(N);
    k_place<<<cdiv(E, 256), 256>>>(ei, E);

    // node embed + edge embed
    k_gemm<128, false, false><<<cdiv(N, 256), 256>>>(x, N, Wn, bn, ph, nullptr, nullptr);
    k_edge_embed<<<cdiv(E, 256), 256>>>(ea, E, We, be, ei, ph);

    const int gw = cdiv(N * 32, 256);   // gather: warp per node

    // GCN layer 1 (no relu on input); gemm seeds ph2 = b1 + t*dinv^2
    k_gemm<64, false, true><<<cdiv(N, 256), 256>>>(ph, N, W1, nullptr, pt, b1, ph2);
    k_gather<<<gw, 256>>>(pt, ph2, N);

    // GCN layer 2 (relu on input); seeds ph = b2 + t*dinv^2
    k_gemm<64, true, true><<<cdiv(N, 256), 256>>>(ph2, N, W2, nullptr, pt, b2, ph);
    k_gather<<<gw, 256>>>(pt, ph, N);

    // GCN layer 3 (relu on input); seeds ph2 = b3 + t*dinv^2
    k_gemm<64, true, true><<<cdiv(N, 256), 256>>>(ph, N, W3, nullptr, pt, b3, ph2);
    k_gather<<<gw, 256>>>(pt, ph2, N);

    // pool + classify
    k_pool<<<64, 256>>>(batch, ph2, N);
    k_classify<<<cdiv(G * 32, 256), 256>>>(Wc1, bc1, Wc2, bc2, out, G);
}

// round 10
// speedup vs baseline: 1.5381x; 1.5381x over previous
#include <cuda_runtime.h>
#include <math.h>

#define HD 64
#define MAXN 100000
#define MAXG 512
#define CAP 80            // max in-degree bucket capacity (Poisson(16) tail ~1e-30)

// ---- scratch (device globals; no allocation allowed) ----
__device__ __align__(128) float  g_h [MAXN * HD];
__device__ __align__(128) float  g_h2[MAXN * HD];
__device__ __align__(128) float  g_t [MAXN * HD];
__device__ __align__(128) float  g_eagg[MAXN * 32];            // summed edge_attr per src
__device__ __align__(128) float  g_dinv[MAXN];
__device__ __align__(128) float  g_odeg[MAXN];                 // out-degree (float)
__device__ __align__(128) float  g_pool[MAXG * HD];
__device__ __align__(128) float  g_cnt [MAXG];
__device__ __align__(128) int    g_fill[MAXN];                 // in-degree fill counter
__device__ __align__(128) float2 g_bucket[(size_t)MAXN * CAP]; // {bits(src), nrm}
__device__ int g_is64;

__device__ __forceinline__ void red_v4(float* p, float4 v) {
    asm volatile("red.global.add.v4.f32 [%0], {%1,%2,%3,%4};"
                 :: "l"(p), "f"(v.x), "f"(v.y), "f"(v.z), "f"(v.w) : "memory");
}

// ---------------------------------------------------------------------------
// setup: dtype detect (idx in [0,100000): int64 => odd words all zero) +
// zero/seed all scratch. eagg zeroed via float4.
// ---------------------------------------------------------------------------
__global__ void k_setup(const int* __restrict__ ei, int n, int g) {
    int i = blockIdx.x * blockDim.x + threadIdx.x;
    if (i == 0) {
        int allz = 1, anynz = 0;
        for (int k = 0; k < 256; k += 2) {
            if (ei[k + 1] != 0) allz = 0;
            if (ei[k]     != 0) anynz = 1;
        }
        g_is64 = (allz && anynz) ? 1 : 0;
    }
    if (i < n) { g_dinv[i] = 1.0f; g_fill[i] = 0; g_odeg[i] = 0.f; }
    if (i < g * HD) g_pool[i] = 0.0f;
    if (i < g)      g_cnt[i]  = 0.0f;
    if (i < n * 8)  ((float4*)g_eagg)[i] = make_float4(0.f, 0.f, 0.f, 0.f);
}

// in-degree only (-> g_dinv); out-degree is folded into k_place
__global__ void k_deg(const void* __restrict__ ei, int E) {
    int is64 = g_is64;
    int i = blockIdx.x * blockDim.x + threadIdx.x;
    if (i < E) {
        int d = is64 ? (int)((const long long*)ei)[(long long)E + i]
                     : ((const int*)ei)[E + i];
        atomicAdd(&g_dinv[d], 1.0f);
    }
}

__global__ void k_dinv(int n) {
    int i = blockIdx.x * blockDim.x + threadIdx.x;
    if (i < n) g_dinv[i] = rsqrtf(g_dinv[i]);   // deg >= 1 always (self loop)
}

// place each edge into its destination bucket: {src, dinv[s]*dinv[d]};
// also accumulate out-degree (only consumed later by k_gemm_node).
__global__ void k_place(const void* __restrict__ ei, int E) {
    int is64 = g_is64;
    int e = blockIdx.x * blockDim.x + threadIdx.x;
    if (e < E) {
        int s, d;
        if (is64) {
            s = (int)((const long long*)ei)[e];
            d = (int)((const long long*)ei)[(long long)E + e];
        } else {
            s = ((const int*)ei)[e];
            d = ((const int*)ei)[E + e];
        }
        float nrm = g_dinv[s] * g_dinv[d];
        int slot = atomicAdd(&g_fill[d], 1);
        if (slot < CAP)
            g_bucket[(size_t)d * CAP + slot] = make_float2(__int_as_float(s), nrm);
        atomicAdd(&g_odeg[s], 1.0f);
    }
}

// eagg[src] += edge_attr[e]  (quarter-warp per edge: 8 lanes x float4 = 128B)
__global__ void k_scatter_ea(const float* __restrict__ EA,
                             const void* __restrict__ ei, int E) {
    const int is64 = g_is64;
    const int lane = threadIdx.x & 7;
    int q  = (blockIdx.x * blockDim.x + threadIdx.x) >> 3;
    int nq = (gridDim.x * blockDim.x) >> 3;
    for (int e = q; e < E; e += nq) {
        int s = is64 ? (int)((const long long*)ei)[e] : ((const int*)ei)[e];
        float4 v = ((const float4*)(EA + (size_t)e * 32))[lane];
        red_v4(g_eagg + (size_t)s * 32 + lane * 4, v);
    }
}

// ---------------------------------------------------------------------------
// Fused node embed: out[r] = x[r]@Wn + eagg[r]@We + bn + odeg[r]*be
// Thread-per-row; W chunk in smem (uniform broadcast LDS.128); A tiles staged
// in smem pad-33 (conflict-free).
// ---------------------------------------------------------------------------
__global__ __launch_bounds__(256)
void k_gemm_node(const float* __restrict__ x, int n,
                 const float* __restrict__ Wn, const float* __restrict__ bn,
                 const float* __restrict__ We, const float* __restrict__ be,
                 float* __restrict__ out) {
    __shared__ float ws[32 * 64];
    __shared__ float as[256 * 33];
    const int tid = threadIdx.x;
    const int r0  = blockIdx.x * 256;
    const int r   = r0 + tid;

    float4 acc[16];
    #pragma unroll
    for (int j = 0; j < 16; j++) acc[j] = make_float4(0.f, 0.f, 0.f, 0.f);

    // phase 1: x @ Wn   (K = 128, 4 chunks)
    for (int kc = 0; kc < 128; kc += 32) {
        __syncthreads();
        #pragma unroll
        for (int i = tid; i < 512; i += 256)
            ((float4*)ws)[i] = ((const float4*)Wn)[kc * 16 + i];
        #pragma unroll
        for (int q = 0; q < 8; q++) {
            int f = tid + 256 * q;
            int row = f >> 3, c4 = f & 7;
            int gr = r0 + row;
            float4 v = make_float4(0.f, 0.f, 0.f, 0.f);
            if (gr < n) v = *(const float4*)(x + (size_t)gr * 128 + kc + c4 * 4);
            float* dst = &as[row * 33 + c4 * 4];
            dst[0] = v.x; dst[1] = v.y; dst[2] = v.z; dst[3] = v.w;
        }
        __syncthreads();
        #pragma unroll 8
        for (int k = 0; k < 32; k++) {
            float a = as[tid * 33 + k];
            const float4* w4 = (const float4*)(ws + k * 64);
            #pragma unroll
            for (int j = 0; j < 16; j++) {
                float4 w = w4[j];
                acc[j].x += a * w.x; acc[j].y += a * w.y;
                acc[j].z += a * w.z; acc[j].w += a * w.w;
            }
        }
    }

    // phase 2: eagg @ We   (K = 32, 1 chunk)
    __syncthreads();
    #pragma unroll
    for (int i = tid; i < 512; i += 256)
        ((float4*)ws)[i] = ((const float4*)We)[i];
    #pragma unroll
    for (int q = 0; q < 8; q++) {
        int f = tid + 256 * q;
        int row = f >> 3, c4 = f & 7;
        int gr = r0 + row;
        float4 v = make_float4(0.f, 0.f, 0.f, 0.f);
        if (gr < n) v = *(const float4*)(g_eagg + (size_t)gr * 32 + c4 * 4);
        float* dst = &as[row * 33 + c4 * 4];
        dst[0] = v.x; dst[1] = v.y; dst[2] = v.z; dst[3] = v.w;
    }
    __syncthreads();
    #pragma unroll 8
    for (int k = 0; k < 32; k++) {
        float a = as[tid * 33 + k];
        const float4* w4 = (const float4*)(ws + k * 64);
        #pragma unroll
        for (int j = 0; j < 16; j++) {
            float4 w = w4[j];
            acc[j].x += a * w.x; acc[j].y += a * w.y;
            acc[j].z += a * w.z; acc[j].w += a * w.w;
        }
    }

    if (r < n) {
        float od = g_odeg[r];
        float4* o = (float4*)(out + (size_t)r * HD);
        #pragma unroll
        for (int j = 0; j < 16; j++) {
            float4 b  = ((const float4*)bn)[j];
            float4 eb = ((const float4*)be)[j];
            float4 v;
            v.x = acc[j].x + b.x + od * eb.x;
            v.y = acc[j].y + b.y + od * eb.y;
            v.z = acc[j].z + b.z + od * eb.z;
            v.w = acc[j].w + b.w + od * eb.w;
            o[j] = v;
        }
    }
}

// ---------------------------------------------------------------------------
// Layer GEMM: out[r,:] = (RELU? relu(A[r,:]) : A[r,:]) @ W   (K=64)
// Also seeds out2[r,:] = bias2 + out[r,:] * dinv[r]^2  (fused self-loop+bias)
// ---------------------------------------------------------------------------
template<bool RELU>
__global__ __launch_bounds__(256)
void k_gemm(const float* __restrict__ A, int n,
            const float* __restrict__ W,
            float* __restrict__ out,
            const float* __restrict__ bias2, float* __restrict__ out2) {
    __shared__ float ws[32 * 64];
    __shared__ float as[256 * 33];
    const int tid = threadIdx.x;
    const int r0  = blockIdx.x * 256;
    const int r   = r0 + tid;

    float4 acc[16];
    #pragma unroll
    for (int j = 0; j < 16; j++) acc[j] = make_float4(0.f, 0.f, 0.f, 0.f);

    for (int kc = 0; kc < 64; kc += 32) {
        __syncthreads();
        #pragma unroll
        for (int i = tid; i < 512; i += 256)
            ((float4*)ws)[i] = ((const float4*)W)[kc * 16 + i];
        #pragma unroll
        for (int q = 0; q < 8; q++) {
            int f = tid + 256 * q;
            int row = f >> 3, c4 = f & 7;
            int gr = r0 + row;
            float4 v = make_float4(0.f, 0.f, 0.f, 0.f);
            if (gr < n) v = *(const float4*)(A + (size_t)gr * 64 + kc + c4 * 4);
            if (RELU) {
                v.x = fmaxf(v.x, 0.f); v.y = fmaxf(v.y, 0.f);
                v.z = fmaxf(v.z, 0.f); v.w = fmaxf(v.w, 0.f);
            }
            float* dst = &as[row * 33 + c4 * 4];
            dst[0] = v.x; dst[1] = v.y; dst[2] = v.z; dst[3] = v.w;
        }
        __syncthreads();
        #pragma unroll 8
        for (int k = 0; k < 32; k++) {
            float a = as[tid * 33 + k];
            const float4* w4 = (const float4*)(ws + k * 64);
            #pragma unroll
            for (int j = 0; j < 16; j++) {
                float4 w = w4[j];
                acc[j].x += a * w.x; acc[j].y += a * w.y;
                acc[j].z += a * w.z; acc[j].w += a * w.w;
            }
        }
    }
    if (r < n) {
        float4* o  = (float4*)(out  + (size_t)r * HD);
        float4* o2 = (float4*)(out2 + (size_t)r * HD);
        float di = g_dinv[r];
        float s  = di * di;
        #pragma unroll
        for (int j = 0; j < 16; j++) {
            o[j] = acc[j];
            float4 b = ((const float4*)bias2)[j];
            float4 v;
            v.x = b.x + acc[j].x * s; v.y = b.y + acc[j].y * s;
            v.z = b.z + acc[j].z * s; v.w = b.w + acc[j].w * s;
            o2[j] = v;
        }
    }
}

// ---------------------------------------------------------------------------
// Gather aggregation: warp per node; out[n] (pre-seeded with bias + self term)
// += sum over in-edges of t[src] * nrm. No atomics — warp owns the row.
// 4-way unroll for MLP.
// ---------------------------------------------------------------------------
__global__ __launch_bounds__(256)
void k_gather(const float* __restrict__ t, float* __restrict__ out, int N) {
    int warp = (blockIdx.x * blockDim.x + threadIdx.x) >> 5;
    int lane = threadIdx.x & 31;
    if (warp >= N) return;
    int deg = g_fill[warp];
    if (deg > CAP) deg = CAP;
    const float2* bk = &g_bucket[(size_t)warp * CAP];
    float* op = out + (size_t)warp * HD;
    float a0 = op[lane], a1 = op[lane + 32];
    int i = 0;
    for (; i + 4 <= deg; i += 4) {
        float2 r0 = bk[i], r1 = bk[i + 1], r2 = bk[i + 2], r3 = bk[i + 3];
        const float* t0 = t + (size_t)__float_as_int(r0.x) * HD;
        const float* t1 = t + (size_t)__float_as_int(r1.x) * HD;
        const float* t2 = t + (size_t)__float_as_int(r2.x) * HD;
        const float* t3 = t + (size_t)__float_as_int(r3.x) * HD;
        float v00 = t0[lane], v01 = t0[lane + 32];
        float v10 = t1[lane], v11 = t1[lane + 32];
        float v20 = t2[lane], v21 = t2[lane + 32];
        float v30 = t3[lane], v31 = t3[lane + 32];
        a0 += v00 * r0.y + v10 * r1.y + v20 * r2.y + v30 * r3.y;
        a1 += v01 * r0.y + v11 * r1.y + v21 * r2.y + v31 * r3.y;
    }
    for (; i < deg; i++) {
        float2 rr = bk[i];
        const float* ts = t + (size_t)__float_as_int(rr.x) * HD;
        a0 += ts[lane] * rr.y;
        a1 += ts[lane + 32] * rr.y;
    }
    op[lane] = a0; op[lane + 32] = a1;
}

// sorted-batch mean-pool: warp per contiguous node chunk, register accumulate,
// flush on graph-id boundary.
__global__ void k_pool(const void* __restrict__ batch,
                       const float* __restrict__ h, int N) {
    const int is64 = g_is64;
    const int lane = threadIdx.x & 31;
    int warp = (blockIdx.x * blockDim.x + threadIdx.x) >> 5;
    int nw   = (gridDim.x * blockDim.x) >> 5;
    int chunk = (N + nw - 1) / nw;
    int n0 = warp * chunk;
    int n1 = min(N, n0 + chunk);
    float a0 = 0.f, a1 = 0.f, c = 0.f;
    int cur = -1;
    for (int n = n0; n < n1; n++) {
        int b = is64 ? (int)((const long long*)batch)[n] : ((const int*)batch)[n];
        if (b != cur) {
            if (cur >= 0) {
                atomicAdd(&g_pool[cur * HD + lane],      a0);
                atomicAdd(&g_pool[cur * HD + 32 + lane], a1);
                if (lane == 0) atomicAdd(&g_cnt[cur], c);
            }
            cur = b; a0 = a1 = 0.f; c = 0.f;
        }
        a0 += h[(size_t)n * HD + lane];
        a1 += h[(size_t)n * HD + 32 + lane];
        c  += 1.0f;
    }
    if (cur >= 0) {
        atomicAdd(&g_pool[cur * HD + lane],      a0);
        atomicAdd(&g_pool[cur * HD + 32 + lane], a1);
        if (lane == 0) atomicAdd(&g_cnt[cur], c);
    }
}

// warp-per-graph classifier: relu(mean @ Wc1 + bc1) @ Wc2 + bc2
__global__ void k_classify(const float* __restrict__ Wc1, const float* __restrict__ bc1,
                           const float* __restrict__ Wc2, const float* __restrict__ bc2,
                           float* __restrict__ out, int G) {
    int warp = (blockIdx.x * blockDim.x + threadIdx.x) >> 5;
    int lane = threadIdx.x & 31;
    if (warp >= G) return;
    float inv = 1.0f / fmaxf(g_cnt[warp], 1.0f);
    float c1 = bc1[lane];
    #pragma unroll 8
    for (int k = 0; k < HD; k++) {
        float m = g_pool[warp * HD + k] * inv;
        c1 += m * Wc1[k * 32 + lane];
    }
    c1 = fmaxf(c1, 0.f);
    float v = c1 * Wc2[lane];
    #pragma unroll
    for (int off = 16; off; off >>= 1)
        v += __shfl_down_sync(0xffffffffu, v, off);
    if (lane == 0) out[warp] = v + bc2[0];
}

static inline int cdiv(int a, int b) { return (a + b - 1) / b; }

extern "C" void kernel_launch(void* const* d_in, const int* in_sizes, int n_in,
                              void* d_out, int out_size) {
    const float* x     = (const float*)d_in[0];
    const void*  ei    = d_in[1];
    const float* ea    = (const float*)d_in[2];
    const void*  batch = d_in[3];
    const float* Wn  = (const float*)d_in[4];  const float* bn  = (const float*)d_in[5];
    const float* We  = (const float*)d_in[6];  const float* be  = (const float*)d_in[7];
    const float* W1  = (const float*)d_in[8];  const float* b1  = (const float*)d_in[9];
    const float* W2  = (const float*)d_in[10]; const float* b2  = (const float*)d_in[11];
    const float* W3  = (const float*)d_in[12]; const float* b3  = (const float*)d_in[13];
    const float* Wc1 = (const float*)d_in[14]; const float* bc1 = (const float*)d_in[15];
    const float* Wc2 = (const float*)d_in[16]; const float* bc2 = (const float*)d_in[17];
    float* out = (float*)d_out;

    const int N = in_sizes[3];        // batch has N elements
    const int E = in_sizes[2] / 32;   // edge_attr is [E,32]
    const int G = out_size;

    float *ph, *ph2, *pt;
    cudaGetSymbolAddress((void**)&ph,  g_h);
    cudaGetSymbolAddress((void**)&ph2, g_h2);
    cudaGetSymbolAddress((void**)&pt,  g_t);

    // setup covers max(N, G*HD, N*8) threads
    int setupN = N * 8;
    if (G * HD > setupN) setupN = G * HD;
    k_setup<<<cdiv(setupN, 256), 256>>>((const int*)ei, N, G);
    k_deg  <<<cdiv(E, 256), 256>>>(ei, E);
    k_dinv <<<cdiv(N, 256), 256>>>(N);
    k_place<<<cdiv(E, 256), 256>>>(ei, E);
    k_scatter_ea<<<2048, 256>>>(ea, ei, E);

    // fused node embed: x@Wn + eagg@We + bn + odeg*be
    k_gemm_node<<<cdiv(N, 256), 256>>>(x, N, Wn, bn, We, be, ph);

    const int gw = cdiv(N * 32, 256);   // gather: warp per node

    // GCN layer 1 (no relu on input); gemm seeds ph2 = b1 + t*dinv^2
    k_gemm<false><<<cdiv(N, 256), 256>>>(ph, N, W1, pt, b1, ph2);
    k_gather<<<gw, 256>>>(pt, ph2, N);

    // GCN layer 2 (relu on input); seeds ph = b2 + t*dinv^2
    k_gemm<true><<<cdiv(N, 256), 256>>>(ph2, N, W2, pt, b2, ph);
    k_gather<<<gw, 256>>>(pt, ph, N);

    // GCN layer 3 (relu on input); seeds ph2 = b3 + t*dinv^2
    k_gemm<true><<<cdiv(N, 256), 256>>>(ph, N, W3, pt, b3, ph2);
    k_gather<<<gw, 256>>>(pt, ph2, N);

    // pool + classify
    k_pool<<<64, 256>>>(batch, ph2, N);
    k_classify<<<cdiv(G * 32, 256), 256>>>(Wc1, bc1, Wc2, bc2, out, G);
}

// round 12
// speedup vs baseline: 1.5979x; 1.0389x over previous
#include <cuda_runtime.h>
#include <math.h>

#define HD 64
#define MAXN 100000
#define MAXG 512
#define CAP 80            // max in-degree bucket capacity (Poisson(16) tail ~1e-30)

// ---- scratch (device globals; no allocation allowed) ----
__device__ __align__(128) float  g_h [MAXN * HD];
__device__ __align__(128) float  g_h2[MAXN * HD];
__device__ __align__(128) float  g_t [MAXN * HD];
__device__ __align__(128) float  g_eagg[MAXN * 32];            // summed edge_attr per src
__device__ __align__(128) float  g_dinv[MAXN];
__device__ __align__(128) float  g_odeg[MAXN];                 // out-degree (float)
__device__ __align__(128) float  g_pool[MAXG * HD];
__device__ __align__(128) float  g_cnt [MAXG];
__device__ __align__(128) int    g_fill[MAXN];                 // in-degree fill counter
__device__ __align__(128) int    g_bucket[(size_t)MAXN * CAP]; // src index per in-edge
__device__ int g_is64;

__device__ __forceinline__ void red_v4(float* p, float4 v) {
    asm volatile("red.global.add.v4.f32 [%0], {%1,%2,%3,%4};"
                 :: "l"(p), "f"(v.x), "f"(v.y), "f"(v.z), "f"(v.w) : "memory");
}

// ---------------------------------------------------------------------------
// setup: dtype detect (idx in [0,100000): int64 => odd words all zero) +
// zero/seed all scratch. eagg zeroed via float4.
// ---------------------------------------------------------------------------
__global__ void k_setup(const int* __restrict__ ei, int n, int g) {
    int i = blockIdx.x * blockDim.x + threadIdx.x;
    if (i == 0) {
        int allz = 1, anynz = 0;
        for (int k = 0; k < 256; k += 2) {
            if (ei[k + 1] != 0) allz = 0;
            if (ei[k]     != 0) anynz = 1;
        }
        g_is64 = (allz && anynz) ? 1 : 0;
    }
    if (i < n) { g_fill[i] = 0; g_odeg[i] = 0.f; }
    if (i < g * HD) g_pool[i] = 0.0f;
    if (i < g)      g_cnt[i]  = 0.0f;
    if (i < n * 8)  ((float4*)g_eagg)[i] = make_float4(0.f, 0.f, 0.f, 0.f);
}

// place each edge into its destination bucket (src only; 4B/edge);
// in-degree accumulates in g_fill; out-degree (float) for k_gemm_node.
__global__ void k_place(const void* __restrict__ ei, int E) {
    int is64 = g_is64;
    int e = blockIdx.x * blockDim.x + threadIdx.x;
    if (e < E) {
        int s, d;
        if (is64) {
            s = (int)((const long long*)ei)[e];
            d = (int)((const long long*)ei)[(long long)E + e];
        } else {
            s = ((const int*)ei)[e];
            d = ((const int*)ei)[E + e];
        }
        int slot = atomicAdd(&g_fill[d], 1);
        if (slot < CAP)
            g_bucket[(size_t)d * CAP + slot] = s;
        atomicAdd(&g_odeg[s], 1.0f);
    }
}

// dinv from fill counters (deg = fill + 1 self loop)
__global__ void k_dinv(int n) {
    int i = blockIdx.x * blockDim.x + threadIdx.x;
    if (i < n) g_dinv[i] = rsqrtf(1.0f + (float)g_fill[i]);
}

// eagg[src] += edge_attr[e]  (quarter-warp per edge: 8 lanes x float4 = 128B)
__global__ void k_scatter_ea(const float* __restrict__ EA,
                             const void* __restrict__ ei, int E) {
    const int is64 = g_is64;
    const int lane = threadIdx.x & 7;
    int q  = (blockIdx.x * blockDim.x + threadIdx.x) >> 3;
    int nq = (gridDim.x * blockDim.x) >> 3;
    for (int e = q; e < E; e += nq) {
        int s = is64 ? (int)((const long long*)ei)[e] : ((const int*)ei)[e];
        float4 v = ((const float4*)(EA + (size_t)e * 32))[lane];
        red_v4(g_eagg + (size_t)s * 32 + lane * 4, v);
    }
}

// ---------------------------------------------------------------------------
// Fused node embed: out[r] = x[r]@Wn + eagg[r]@We + bn + odeg[r]*be
// Thread-per-row; W chunk in smem (uniform broadcast LDS.128); A tiles staged
// in smem pad-33 (conflict-free).
// ---------------------------------------------------------------------------
__global__ __launch_bounds__(256)
void k_gemm_node(const float* __restrict__ x, int n,
                 const float* __restrict__ Wn, const float* __restrict__ bn,
                 const float* __restrict__ We, const float* __restrict__ be,
                 float* __restrict__ out) {
    __shared__ float ws[32 * 64];
    __shared__ float as[256 * 33];
    const int tid = threadIdx.x;
    const int r0  = blockIdx.x * 256;
    const int r   = r0 + tid;

    float4 acc[16];
    #pragma unroll
    for (int j = 0; j < 16; j++) acc[j] = make_float4(0.f, 0.f, 0.f, 0.f);

    // phase 1: x @ Wn   (K = 128, 4 chunks)
    for (int kc = 0; kc < 128; kc += 32) {
        __syncthreads();
        #pragma unroll
        for (int i = tid; i < 512; i += 256)
            ((float4*)ws)[i] = ((const float4*)Wn)[kc * 16 + i];
        #pragma unroll
        for (int q = 0; q < 8; q++) {
            int f = tid + 256 * q;
            int row = f >> 3, c4 = f & 7;
            int gr = r0 + row;
            float4 v = make_float4(0.f, 0.f, 0.f, 0.f);
            if (gr < n) v = *(const float4*)(x + (size_t)gr * 128 + kc + c4 * 4);
            float* dst = &as[row * 33 + c4 * 4];
            dst[0] = v.x; dst[1] = v.y; dst[2] = v.z; dst[3] = v.w;
        }
        __syncthreads();
        #pragma unroll 8
        for (int k = 0; k < 32; k++) {
            float a = as[tid * 33 + k];
            const float4* w4 = (const float4*)(ws + k * 64);
            #pragma unroll
            for (int j = 0; j < 16; j++) {
                float4 w = w4[j];
                acc[j].x += a * w.x; acc[j].y += a * w.y;
                acc[j].z += a * w.z; acc[j].w += a * w.w;
            }
        }
    }

    // phase 2: eagg @ We   (K = 32, 1 chunk)
    __syncthreads();
    #pragma unroll
    for (int i = tid; i < 512; i += 256)
        ((float4*)ws)[i] = ((const float4*)We)[i];
    #pragma unroll
    for (int q = 0; q < 8; q++) {
        int f = tid + 256 * q;
        int row = f >> 3, c4 = f & 7;
        int gr = r0 + row;
        float4 v = make_float4(0.f, 0.f, 0.f, 0.f);
        if (gr < n) v = *(const float4*)(g_eagg + (size_t)gr * 32 + c4 * 4);
        float* dst = &as[row * 33 + c4 * 4];
        dst[0] = v.x; dst[1] = v.y; dst[2] = v.z; dst[3] = v.w;
    }
    __syncthreads();
    #pragma unroll 8
    for (int k = 0; k < 32; k++) {
        float a = as[tid * 33 + k];
        const float4* w4 = (const float4*)(ws + k * 64);
        #pragma unroll
        for (int j = 0; j < 16; j++) {
            float4 w = w4[j];
            acc[j].x += a * w.x; acc[j].y += a * w.y;
            acc[j].z += a * w.z; acc[j].w += a * w.w;
        }
    }

    if (r < n) {
        float od = g_odeg[r];
        float4* o = (float4*)(out + (size_t)r * HD);
        #pragma unroll
        for (int j = 0; j < 16; j++) {
            float4 b  = ((const float4*)bn)[j];
            float4 eb = ((const float4*)be)[j];
            float4 v;
            v.x = acc[j].x + b.x + od * eb.x;
            v.y = acc[j].y + b.y + od * eb.y;
            v.z = acc[j].z + b.z + od * eb.z;
            v.w = acc[j].w + b.w + od * eb.w;
            o[j] = v;
        }
    }
}

// ---------------------------------------------------------------------------
// Layer GEMM: acc = (RELU? relu(A[r,:]) : A[r,:]) @ W   (K=64)
// Writes out[r]  = acc * dinv[r]          (pre-scaled for the gather)
//        out2[r] = bias2 + acc*dinv[r]^2  (self-loop + bias seed)
// ---------------------------------------------------------------------------
template<bool RELU>
__global__ __launch_bounds__(256)
void k_gemm(const float* __restrict__ A, int n,
            const float* __restrict__ W,
            float* __restrict__ out,
            const float* __restrict__ bias2, float* __restrict__ out2) {
    __shared__ float ws[32 * 64];
    __shared__ float as[256 * 33];
    const int tid = threadIdx.x;
    const int r0  = blockIdx.x * 256;
    const int r   = r0 + tid;

    float4 acc[16];
    #pragma unroll
    for (int j = 0; j < 16; j++) acc[j] = make_float4(0.f, 0.f, 0.f, 0.f);

    for (int kc = 0; kc < 64; kc += 32) {
        __syncthreads();
        #pragma unroll
        for (int i = tid; i < 512; i += 256)
            ((float4*)ws)[i] = ((const float4*)W)[kc * 16 + i];
        #pragma unroll
        for (int q = 0; q < 8; q++) {
            int f = tid + 256 * q;
            int row = f >> 3, c4 = f & 7;
            int gr = r0 + row;
            float4 v = make_float4(0.f, 0.f, 0.f, 0.f);
            if (gr < n) v = *(const float4*)(A + (size_t)gr * 64 + kc + c4 * 4);
            if (RELU) {
                v.x = fmaxf(v.x, 0.f); v.y = fmaxf(v.y, 0.f);
                v.z = fmaxf(v.z, 0.f); v.w = fmaxf(v.w, 0.f);
            }
            float* dst = &as[row * 33 + c4 * 4];
            dst[0] = v.x; dst[1] = v.y; dst[2] = v.z; dst[3] = v.w;
        }
        __syncthreads();
        #pragma unroll 8
        for (int k = 0; k < 32; k++) {
            float a = as[tid * 33 + k];
            const float4* w4 = (const float4*)(ws + k * 64);
            #pragma unroll
            for (int j = 0; j < 16; j++) {
                float4 w = w4[j];
                acc[j].x += a * w.x; acc[j].y += a * w.y;
                acc[j].z += a * w.z; acc[j].w += a * w.w;
            }
        }
    }
    if (r < n) {
        float4* o  = (float4*)(out  + (size_t)r * HD);
        float4* o2 = (float4*)(out2 + (size_t)r * HD);
        float di = g_dinv[r];
        #pragma unroll
        for (int j = 0; j < 16; j++) {
            float4 ts;
            ts.x = acc[j].x * di; ts.y = acc[j].y * di;
            ts.z = acc[j].z * di; ts.w = acc[j].w * di;
            o[j] = ts;
            float4 b = ((const float4*)bias2)[j];
            float4 v;
            v.x = b.x + ts.x * di; v.y = b.y + ts.y * di;
            v.z = b.z + ts.z * di; v.w = b.w + ts.w * di;
            o2[j] = v;
        }
    }
}

// ---------------------------------------------------------------------------
// Gather aggregation: warp per node; out[n] (pre-seeded with bias + self term)
// += dinv[n] * sum over in-edges of t'[src]  (t' pre-scaled by dinv[src]).
// No atomics — warp owns the row. 4-way unroll, int4 index loads.
// ---------------------------------------------------------------------------
__global__ __launch_bounds__(256)
void k_gather(const float* __restrict__ t, float* __restrict__ out, int N) {
    int warp = (blockIdx.x * blockDim.x + threadIdx.x) >> 5;
    int lane = threadIdx.x & 31;
    if (warp >= N) return;
    int deg = g_fill[warp];
    if (deg > CAP) deg = CAP;
    const int* bk = &g_bucket[(size_t)warp * CAP];
    float dn = g_dinv[warp];
    float* op = out + (size_t)warp * HD;
    float a0 = 0.f, a1 = 0.f;
    int i = 0;
    for (; i + 4 <= deg; i += 4) {
        int4 q = *(const int4*)(bk + i);        // broadcast LDG.128: 4 src idx
        const float* t0 = t + (size_t)q.x * HD;
        const float* t1 = t + (size_t)q.y * HD;
        const float* t2 = t + (size_t)q.z * HD;
        const float* t3 = t + (size_t)q.w * HD;
        float v00 = t0[lane], v01 = t0[lane + 32];
        float v10 = t1[lane], v11 = t1[lane + 32];
        float v20 = t2[lane], v21 = t2[lane + 32];
        float v30 = t3[lane], v31 = t3[lane + 32];
        a0 += (v00 + v10) + (v20 + v30);
        a1 += (v01 + v11) + (v21 + v31);
    }
    for (; i < deg; i++) {
        const float* ts = t + (size_t)bk[i] * HD;
        a0 += ts[lane];
        a1 += ts[lane + 32];
    }
    op[lane]      += dn * a0;
    op[lane + 32] += dn * a1;
}

// sorted-batch mean-pool: warp per contiguous node chunk, register accumulate,
// flush on graph-id boundary.
__global__ void k_pool(const void* __restrict__ batch,
                       const float* __restrict__ h, int N) {
    const int is64 = g_is64;
    const int lane = threadIdx.x & 31;
    int warp = (blockIdx.x * blockDim.x + threadIdx.x) >> 5;
    int nw   = (gridDim.x * blockDim.x) >> 5;
    int chunk = (N + nw - 1) / nw;
    int n0 = warp * chunk;
    int n1 = min(N, n0 + chunk);
    float a0 = 0.f, a1 = 0.f, c = 0.f;
    int cur = -1;
    for (int n = n0; n < n1; n++) {
        int b = is64 ? (int)((const long long*)batch)[n] : ((const int*)batch)[n];
        if (b != cur) {
            if (cur >= 0) {
                atomicAdd(&g_pool[cur * HD + lane],      a0);
                atomicAdd(&g_pool[cur * HD + 32 + lane], a1);
                if (lane == 0) atomicAdd(&g_cnt[cur], c);
            }
            cur = b; a0 = a1 = 0.f; c = 0.f;
        }
        a0 += h[(size_t)n * HD + lane];
        a1 += h[(size_t)n * HD + 32 + lane];
        c  += 1.0f;
    }
    if (cur >= 0) {
        atomicAdd(&g_pool[cur * HD + lane],      a0);
        atomicAdd(&g_pool[cur * HD + 32 + lane], a1);
        if (lane == 0) atomicAdd(&g_cnt[cur], c);
    }
}

// warp-per-graph classifier: relu(mean @ Wc1 + bc1) @ Wc2 + bc2
__global__ void k_classify(const float* __restrict__ Wc1, const float* __restrict__ bc1,
                           const float* __restrict__ Wc2, const float* __restrict__ bc2,
                           float* __restrict__ out, int G) {
    int warp = (blockIdx.x * blockDim.x + threadIdx.x) >> 5;
    int lane = threadIdx.x & 31;
    if (warp >= G) return;
    float inv = 1.0f / fmaxf(g_cnt[warp], 1.0f);
    float c1 = bc1[lane];
    #pragma unroll 8
    for (int k = 0; k < HD; k++) {
        float m = g_pool[warp * HD + k] * inv;
        c1 += m * Wc1[k * 32 + lane];
    }
    c1 = fmaxf(c1, 0.f);
    float v = c1 * Wc2[lane];
    #pragma unroll
    for (int off = 16; off; off >>= 1)
        v += __shfl_down_sync(0xffffffffu, v, off);
    if (lane == 0) out[warp] = v + bc2[0];
}

static inline int cdiv(int a, int b) { return (a + b - 1) / b; }

extern "C" void kernel_launch(void* const* d_in, const int* in_sizes, int n_in,
                              void* d_out, int out_size) {
    const float* x     = (const float*)d_in[0];
    const void*  ei    = d_in[1];
    const float* ea    = (const float*)d_in[2];
    const void*  batch = d_in[3];
    const float* Wn  = (const float*)d_in[4];  const float* bn  = (const float*)d_in[5];
    const float* We  = (const float*)d_in[6];  const float* be  = (const float*)d_in[7];
    const float* W1  = (const float*)d_in[8];  const float* b1  = (const float*)d_in[9];
    const float* W2  = (const float*)d_in[10]; const float* b2  = (const float*)d_in[11];
    const float* W3  = (const float*)d_in[12]; const float* b3  = (const float*)d_in[13];
    const float* Wc1 = (const float*)d_in[14]; const float* bc1 = (const float*)d_in[15];
    const float* Wc2 = (const float*)d_in[16]; const float* bc2 = (const float*)d_in[17];
    float* out = (float*)d_out;

    const int N = in_sizes[3];        // batch has N elements
    const int E = in_sizes[2] / 32;   // edge_attr is [E,32]
    const int G = out_size;

    float *ph, *ph2, *pt;
    cudaGetSymbolAddress((void**)&ph,  g_h);
    cudaGetSymbolAddress((void**)&ph2, g_h2);
    cudaGetSymbolAddress((void**)&pt,  g_t);

    // setup covers max(N, G*HD, N*8) threads
    int setupN = N * 8;
    if (G * HD > setupN) setupN = G * HD;
    k_setup<<<cdiv(setupN, 256), 256>>>((const int*)ei, N, G);
    k_place<<<cdiv(E, 256), 256>>>(ei, E);
    k_dinv <<<cdiv(N, 256), 256>>>(N);
    k_scatter_ea<<<2048, 256>>>(ea, ei, E);

    // fused node embed: x@Wn + eagg@We + bn + odeg*be
    k_gemm_node<<<cdiv(N, 256), 256>>>(x, N, Wn, bn, We, be, ph);

    const int gw = cdiv(N * 32, 256);   // gather: warp per node

    // GCN layer 1 (no relu on input); gemm seeds ph2 = b1 + t*dinv^2, t pre-scaled
    k_gemm<false><<<cdiv(N, 256), 256>>>(ph, N, W1, pt, b1, ph2);
    k_gather<<<gw, 256>>>(pt, ph2, N);

    // GCN layer 2 (relu on input); seeds ph
    k_gemm<true><<<cdiv(N, 256), 256>>>(ph2, N, W2, pt, b2, ph);
    k_gather<<<gw, 256>>>(pt, ph, N);

    // GCN layer 3 (relu on input); seeds ph2
    k_gemm<true><<<cdiv(N, 256), 256>>>(ph, N, W3, pt, b3, ph2);
    k_gather<<<gw, 256>>>(pt, ph2, N);

    // pool + classify
    k_pool<<<64, 256>>>(batch, ph2, N);
    k_classify<<<cdiv(G * 32, 256), 256>>>(Wc1, bc1, Wc2, bc2, out, G);
}

// round 13
// speedup vs baseline: 1.7293x; 1.0822x over previous
#include <cuda_runtime.h>
#include <math.h>

#define HD 64
#define MAXN 100000
#define MAXG 512
#define CAP 80            // max in-degree bucket capacity (Poisson(16) tail ~1e-30)

// ---- scratch (device globals; no allocation allowed) ----
__device__ __align__(128) float  g_h [MAXN * HD];
__device__ __align__(128) float  g_h2[MAXN * HD];
__device__ __align__(128) float  g_t [MAXN * HD];
__device__ __align__(128) float  g_eagg[MAXN * 32];            // summed edge_attr per src
__device__ __align__(128) float  g_dinv[MAXN];
__device__ __align__(128) float  g_odeg[MAXN];                 // out-degree (float)
__device__ __align__(128) float  g_pool[MAXG * HD];
__device__ __align__(128) float  g_cnt [MAXG];
__device__ __align__(128) int    g_fill[MAXN];                 // in-degree fill counter
__device__ __align__(128) int    g_bucket[(size_t)MAXN * CAP]; // src index per in-edge
__device__ int g_is64;

__device__ __forceinline__ void red_v4(float* p, float4 v) {
    asm volatile("red.global.add.v4.f32 [%0], {%1,%2,%3,%4};"
                 :: "l"(p), "f"(v.x), "f"(v.y), "f"(v.z), "f"(v.w) : "memory");
}

// ---------------------------------------------------------------------------
// setup: dtype detect (idx in [0,100000): int64 => odd words all zero) +
// zero/seed all scratch. eagg zeroed via float4.
// ---------------------------------------------------------------------------
__global__ void k_setup(const int* __restrict__ ei, int n, int g) {
    int i = blockIdx.x * blockDim.x + threadIdx.x;
    if (i == 0) {
        int allz = 1, anynz = 0;
        for (int k = 0; k < 256; k += 2) {
            if (ei[k + 1] != 0) allz = 0;
            if (ei[k]     != 0) anynz = 1;
        }
        g_is64 = (allz && anynz) ? 1 : 0;
    }
    if (i < n) { g_fill[i] = 0; g_odeg[i] = 0.f; }
    if (i < g * HD) g_pool[i] = 0.0f;
    if (i < g)      g_cnt[i]  = 0.0f;
    if (i < n * 8)  ((float4*)g_eagg)[i] = make_float4(0.f, 0.f, 0.f, 0.f);
}

// place each edge into its destination bucket (src only; 4B/edge);
// in-degree accumulates in g_fill; out-degree (float) for k_gemm_node.
__global__ void k_place(const void* __restrict__ ei, int E) {
    int is64 = g_is64;
    int e = blockIdx.x * blockDim.x + threadIdx.x;
    if (e < E) {
        int s, d;
        if (is64) {
            s = (int)((const long long*)ei)[e];
            d = (int)((const long long*)ei)[(long long)E + e];
        } else {
            s = ((const int*)ei)[e];
            d = ((const int*)ei)[E + e];
        }
        int slot = atomicAdd(&g_fill[d], 1);
        if (slot < CAP)
            g_bucket[(size_t)d * CAP + slot] = s;
        atomicAdd(&g_odeg[s], 1.0f);
    }
}

// dinv from fill counters (deg = fill + 1 self loop)
__global__ void k_dinv(int n) {
    int i = blockIdx.x * blockDim.x + threadIdx.x;
    if (i < n) g_dinv[i] = rsqrtf(1.0f + (float)g_fill[i]);
}

// eagg[src] += edge_attr[e]  (quarter-warp per edge pair: 8 lanes x float4;
// 2-way unroll for DRAM MLP — measured 56.9% of peak without it)
__global__ void k_scatter_ea(const float* __restrict__ EA,
                             const void* __restrict__ ei, int E) {
    const int is64 = g_is64;
    const int lane = threadIdx.x & 7;
    int q  = (blockIdx.x * blockDim.x + threadIdx.x) >> 3;
    int nq = (gridDim.x * blockDim.x) >> 3;
    int e0 = q * 2;
    int stride = nq * 2;
    for (; e0 + 1 < E; e0 += stride) {
        int e1 = e0 + 1;
        int s0, s1;
        if (is64) {
            s0 = (int)((const long long*)ei)[e0];
            s1 = (int)((const long long*)ei)[e1];
        } else {
            s0 = ((const int*)ei)[e0];
            s1 = ((const int*)ei)[e1];
        }
        float4 v0 = ((const float4*)(EA + (size_t)e0 * 32))[lane];
        float4 v1 = ((const float4*)(EA + (size_t)e1 * 32))[lane];
        red_v4(g_eagg + (size_t)s0 * 32 + lane * 4, v0);
        red_v4(g_eagg + (size_t)s1 * 32 + lane * 4, v1);
    }
    if (e0 < E) {   // tail (odd E)
        int s = is64 ? (int)((const long long*)ei)[e0] : ((const int*)ei)[e0];
        float4 v = ((const float4*)(EA + (size_t)e0 * 32))[lane];
        red_v4(g_eagg + (size_t)s * 32 + lane * 4, v);
    }
}

// ---------------------------------------------------------------------------
// Fused node embed: out[r] = x[r]@Wn + eagg[r]@We + bn + odeg[r]*be
// Thread-per-row; W chunk in smem (uniform broadcast LDS.128); A tiles staged
// in smem pad-33 (conflict-free).
// ---------------------------------------------------------------------------
__global__ __launch_bounds__(256)
void k_gemm_node(const float* __restrict__ x, int n,
                 const float* __restrict__ Wn, const float* __restrict__ bn,
                 const float* __restrict__ We, const float* __restrict__ be,
                 float* __restrict__ out) {
    __shared__ float ws[32 * 64];
    __shared__ float as[256 * 33];
    const int tid = threadIdx.x;
    const int r0  = blockIdx.x * 256;
    const int r   = r0 + tid;

    float4 acc[16];
    #pragma unroll
    for (int j = 0; j < 16; j++) acc[j] = make_float4(0.f, 0.f, 0.f, 0.f);

    // phase 1: x @ Wn   (K = 128, 4 chunks)
    for (int kc = 0; kc < 128; kc += 32) {
        __syncthreads();
        #pragma unroll
        for (int i = tid; i < 512; i += 256)
            ((float4*)ws)[i] = ((const float4*)Wn)[kc * 16 + i];
        #pragma unroll
        for (int q = 0; q < 8; q++) {
            int f = tid + 256 * q;
            int row = f >> 3, c4 = f & 7;
            int gr = r0 + row;
            float4 v = make_float4(0.f, 0.f, 0.f, 0.f);
            if (gr < n) v = *(const float4*)(x + (size_t)gr * 128 + kc + c4 * 4);
            float* dst = &as[row * 33 + c4 * 4];
            dst[0] = v.x; dst[1] = v.y; dst[2] = v.z; dst[3] = v.w;
        }
        __syncthreads();
        #pragma unroll 8
        for (int k = 0; k < 32; k++) {
            float a = as[tid * 33 + k];
            const float4* w4 = (const float4*)(ws + k * 64);
            #pragma unroll
            for (int j = 0; j < 16; j++) {
                float4 w = w4[j];
                acc[j].x += a * w.x; acc[j].y += a * w.y;
                acc[j].z += a * w.z; acc[j].w += a * w.w;
            }
        }
    }

    // phase 2: eagg @ We   (K = 32, 1 chunk)
    __syncthreads();
    #pragma unroll
    for (int i = tid; i < 512; i += 256)
        ((float4*)ws)[i] = ((const float4*)We)[i];
    #pragma unroll
    for (int q = 0; q < 8; q++) {
        int f = tid + 256 * q;
        int row = f >> 3, c4 = f & 7;
        int gr = r0 + row;
        float4 v = make_float4(0.f, 0.f, 0.f, 0.f);
        if (gr < n) v = *(const float4*)(g_eagg + (size_t)gr * 32 + c4 * 4);
        float* dst = &as[row * 33 + c4 * 4];
        dst[0] = v.x; dst[1] = v.y; dst[2] = v.z; dst[3] = v.w;
    }
    __syncthreads();
    #pragma unroll 8
    for (int k = 0; k < 32; k++) {
        float a = as[tid * 33 + k];
        const float4* w4 = (const float4*)(ws + k * 64);
        #pragma unroll
        for (int j = 0; j < 16; j++) {
            float4 w = w4[j];
            acc[j].x += a * w.x; acc[j].y += a * w.y;
            acc[j].z += a * w.z; acc[j].w += a * w.w;
        }
    }

    if (r < n) {
        float od = g_odeg[r];
        float4* o = (float4*)(out + (size_t)r * HD);
        #pragma unroll
        for (int j = 0; j < 16; j++) {
            float4 b  = ((const float4*)bn)[j];
            float4 eb = ((const float4*)be)[j];
            float4 v;
            v.x = acc[j].x + b.x + od * eb.x;
            v.y = acc[j].y + b.y + od * eb.y;
            v.z = acc[j].z + b.z + od * eb.z;
            v.w = acc[j].w + b.w + od * eb.w;
            o[j] = v;
        }
    }
}

// ---------------------------------------------------------------------------
// Layer GEMM: acc = (RELU? relu(A[r,:]) : A[r,:]) @ W   (K=64)
// Writes ONLY t'[r] = acc * dinv[r]  (pre-scaled for the gather; the self-loop
// + bias seed is now folded into k_gather since self term = dinv[r]*t'[r]).
// ---------------------------------------------------------------------------
template<bool RELU>
__global__ __launch_bounds__(256)
void k_gemm(const float* __restrict__ A, int n,
            const float* __restrict__ W,
            float* __restrict__ out) {
    __shared__ float ws[32 * 64];
    __shared__ float as[256 * 33];
    const int tid = threadIdx.x;
    const int r0  = blockIdx.x * 256;
    const int r   = r0 + tid;

    float4 acc[16];
    #pragma unroll
    for (int j = 0; j < 16; j++) acc[j] = make_float4(0.f, 0.f, 0.f, 0.f);

    for (int kc = 0; kc < 64; kc += 32) {
        __syncthreads();
        #pragma unroll
        for (int i = tid; i < 512; i += 256)
            ((float4*)ws)[i] = ((const float4*)W)[kc * 16 + i];
        #pragma unroll
        for (int q = 0; q < 8; q++) {
            int f = tid + 256 * q;
            int row = f >> 3, c4 = f & 7;
            int gr = r0 + row;
            float4 v = make_float4(0.f, 0.f, 0.f, 0.f);
            if (gr < n) v = *(const float4*)(A + (size_t)gr * 64 + kc + c4 * 4);
            if (RELU) {
                v.x = fmaxf(v.x, 0.f); v.y = fmaxf(v.y, 0.f);
                v.z = fmaxf(v.z, 0.f); v.w = fmaxf(v.w, 0.f);
            }
            float* dst = &as[row * 33 + c4 * 4];
            dst[0] = v.x; dst[1] = v.y; dst[2] = v.z; dst[3] = v.w;
        }
        __syncthreads();
        #pragma unroll 8
        for (int k = 0; k < 32; k++) {
            float a = as[tid * 33 + k];
            const float4* w4 = (const float4*)(ws + k * 64);
            #pragma unroll
            for (int j = 0; j < 16; j++) {
                float4 w = w4[j];
                acc[j].x += a * w.x; acc[j].y += a * w.y;
                acc[j].z += a * w.z; acc[j].w += a * w.w;
            }
        }
    }
    if (r < n) {
        float4* o = (float4*)(out + (size_t)r * HD);
        float di = g_dinv[r];
        #pragma unroll
        for (int j = 0; j < 16; j++) {
            float4 ts;
            ts.x = acc[j].x * di; ts.y = acc[j].y * di;
            ts.z = acc[j].z * di; ts.w = acc[j].w * di;
            o[j] = ts;
        }
    }
}

// ---------------------------------------------------------------------------
// Gather aggregation: warp per node n; computes the COMPLETE layer output:
//   out[n] = bias + dinv[n] * ( t'[n] + sum over in-edges t'[src] )
// (self-loop term has the same form as neighbor terms since t' = acc*dinv).
// Pure store — no read-modify-write, no atomics. 4-way unroll, int4 idx loads.
// ---------------------------------------------------------------------------
__global__ __launch_bounds__(256)
void k_gather(const float* __restrict__ t, const float* __restrict__ bias,
              float* __restrict__ out, int N) {
    int warp = (blockIdx.x * blockDim.x + threadIdx.x) >> 5;
    int lane = threadIdx.x & 31;
    if (warp >= N) return;
    int deg = g_fill[warp];
    if (deg > CAP) deg = CAP;
    const int* bk = &g_bucket[(size_t)warp * CAP];
    float dn = g_dinv[warp];
    // self term
    const float* tn = t + (size_t)warp * HD;
    float a0 = tn[lane], a1 = tn[lane + 32];
    int i = 0;
    for (; i + 4 <= deg; i += 4) {
        int4 q = *(const int4*)(bk + i);        // broadcast LDG.128: 4 src idx
        const float* t0 = t + (size_t)q.x * HD;
        const float* t1 = t + (size_t)q.y * HD;
        const float* t2 = t + (size_t)q.z * HD;
        const float* t3 = t + (size_t)q.w * HD;
        float v00 = t0[lane], v01 = t0[lane + 32];
        float v10 = t1[lane], v11 = t1[lane + 32];
        float v20 = t2[lane], v21 = t2[lane + 32];
        float v30 = t3[lane], v31 = t3[lane + 32];
        a0 += (v00 + v10) + (v20 + v30);
        a1 += (v01 + v11) + (v21 + v31);
    }
    for (; i < deg; i++) {
        const float* ts = t + (size_t)bk[i] * HD;
        a0 += ts[lane];
        a1 += ts[lane + 32];
    }
    float* op = out + (size_t)warp * HD;
    op[lane]      = bias[lane]      + dn * a0;
    op[lane + 32] = bias[lane + 32] + dn * a1;
}

// sorted-batch mean-pool: warp per contiguous node chunk, register accumulate,
// flush on graph-id boundary.
__global__ void k_pool(const void* __restrict__ batch,
                       const float* __restrict__ h, int N) {
    const int is64 = g_is64;
    const int lane = threadIdx.x & 31;
    int warp = (blockIdx.x * blockDim.x + threadIdx.x) >> 5;
    int nw   = (gridDim.x * blockDim.x) >> 5;
    int chunk = (N + nw - 1) / nw;
    int n0 = warp * chunk;
    int n1 = min(N, n0 + chunk);
    float a0 = 0.f, a1 = 0.f, c = 0.f;
    int cur = -1;
    for (int n = n0; n < n1; n++) {
        int b = is64 ? (int)((const long long*)batch)[n] : ((const int*)batch)[n];
        if (b != cur) {
            if (cur >= 0) {
                atomicAdd(&g_pool[cur * HD + lane],      a0);
                atomicAdd(&g_pool[cur * HD + 32 + lane], a1);
                if (lane == 0) atomicAdd(&g_cnt[cur], c);
            }
            cur = b; a0 = a1 = 0.f; c = 0.f;
        }
        a0 += h[(size_t)n * HD + lane];
        a1 += h[(size_t)n * HD + 32 + lane];
        c  += 1.0f;
    }
    if (cur >= 0) {
        atomicAdd(&g_pool[cur * HD + lane],      a0);
        atomicAdd(&g_pool[cur * HD + 32 + lane], a1);
        if (lane == 0) atomicAdd(&g_cnt[cur], c);
    }
}

// warp-per-graph classifier: relu(mean @ Wc1 + bc1) @ Wc2 + bc2
__global__ void k_classify(const float* __restrict__ Wc1, const float* __restrict__ bc1,
                           const float* __restrict__ Wc2, const float* __restrict__ bc2,
                           float* __restrict__ out, int G) {
    int warp = (blockIdx.x * blockDim.x + threadIdx.x) >> 5;
    int lane = threadIdx.x & 31;
    if (warp >= G) return;
    float inv = 1.0f / fmaxf(g_cnt[warp], 1.0f);
    float c1 = bc1[lane];
    #pragma unroll 8
    for (int k = 0; k < HD; k++) {
        float m = g_pool[warp * HD + k] * inv;
        c1 += m * Wc1[k * 32 + lane];
    }
    c1 = fmaxf(c1, 0.f);
    float v = c1 * Wc2[lane];
    #pragma unroll
    for (int off = 16; off; off >>= 1)
        v += __shfl_down_sync(0xffffffffu, v, off);
    if (lane == 0) out[warp] = v + bc2[0];
}

static inline int cdiv(int a, int b) { return (a + b - 1) / b; }

extern "C" void kernel_launch(void* const* d_in, const int* in_sizes, int n_in,
                              void* d_out, int out_size) {
    const float* x     = (const float*)d_in[0];
    const void*  ei    = d_in[1];
    const float* ea    = (const float*)d_in[2];
    const void*  batch = d_in[3];
    const float* Wn  = (const float*)d_in[4];  const float* bn  = (const float*)d_in[5];
    const float* We  = (const float*)d_in[6];  const float* be  = (const float*)d_in[7];
    const float* W1  = (const float*)d_in[8];  const float* b1  = (const float*)d_in[9];
    const float* W2  = (const float*)d_in[10]; const float* b2  = (const float*)d_in[11];
    const float* W3  = (const float*)d_in[12]; const float* b3  = (const float*)d_in[13];
    const float* Wc1 = (const float*)d_in[14]; const float* bc1 = (const float*)d_in[15];
    const float* Wc2 = (const float*)d_in[16]; const float* bc2 = (const float*)d_in[17];
    float* out = (float*)d_out;

    const int N = in_sizes[3];        // batch has N elements
    const int E = in_sizes[2] / 32;   // edge_attr is [E,32]
    const int G = out_size;

    float *ph, *ph2, *pt;
    cudaGetSymbolAddress((void**)&ph,  g_h);
    cudaGetSymbolAddress((void**)&ph2, g_h2);
    cudaGetSymbolAddress((void**)&pt,  g_t);

    // setup covers max(N, G*HD, N*8) threads
    int setupN = N * 8;
    if (G * HD > setupN) setupN = G * HD;
    k_setup<<<cdiv(setupN, 256), 256>>>((const int*)ei, N, G);
    k_place<<<cdiv(E, 256), 256>>>(ei, E);
    k_dinv <<<cdiv(N, 256), 256>>>(N);
    k_scatter_ea<<<2048, 256>>>(ea, ei, E);

    // fused node embed: x@Wn + eagg@We + bn + odeg*be
    k_gemm_node<<<cdiv(N, 256), 256>>>(x, N, Wn, bn, We, be, ph);

    const int gw = cdiv(N * 32, 256);   // gather: warp per node

    // GCN layer 1 (no relu on input)
    k_gemm<false><<<cdiv(N, 256), 256>>>(ph, N, W1, pt);
    k_gather<<<gw, 256>>>(pt, b1, ph2, N);

    // GCN layer 2 (relu on input)
    k_gemm<true><<<cdiv(N, 256), 256>>>(ph2, N, W2, pt);
    k_gather<<<gw, 256>>>(pt, b2, ph, N);

    // GCN layer 3 (relu on input)
    k_gemm<true><<<cdiv(N, 256), 256>>>(ph, N, W3, pt);
    k_gather<<<gw, 256>>>(pt, b3, ph2, N);

    // pool + classify
    k_pool<<<64, 256>>>(batch, ph2, N);
    k_classify<<<cdiv(G * 32, 256), 256>>>(Wc1, bc1, Wc2, bc2, out, G);
}

// round 17
// speedup vs baseline: 1.7350x; 1.0033x over previous
#include <cuda_runtime.h>
#include <math.h>

#define HD 64
#define MAXN 100000
#define MAXG 512
#define CAP 80            // max in-degree bucket capacity (Poisson(16) tail ~1e-30)

// ---- scratch (device globals; no allocation allowed) ----
__device__ __align__(128) float  g_h [MAXN * HD];
__device__ __align__(128) float  g_h2[MAXN * HD];
__device__ __align__(128) float  g_t [MAXN * HD];
__device__ __align__(128) float  g_eagg[MAXN * 32];            // summed edge_attr per src
__device__ __align__(128) float  g_dinv[MAXN];
__device__ __align__(128) float  g_odeg[MAXN];                 // out-degree (float)
__device__ __align__(128) float  g_pool[MAXG * HD];
__device__ __align__(128) float  g_cnt [MAXG];
__device__ __align__(128) int    g_fill[MAXN];                 // in-degree fill counter
__device__ __align__(128) int    g_bucket[(size_t)MAXN * CAP]; // src index per in-edge
__device__ int g_is64;

__device__ __forceinline__ void red_v4(float* p, float4 v) {
    asm volatile("red.global.add.v4.f32 [%0], {%1,%2,%3,%4};"
                 :: "l"(p), "f"(v.x), "f"(v.y), "f"(v.z), "f"(v.w) : "memory");
}

// ---------------------------------------------------------------------------
// setup: dtype detect (idx in [0,100000): int64 => odd words all zero) +
// zero/seed all scratch. eagg zeroed via float4.
// ---------------------------------------------------------------------------
__global__ void k_setup(const int* __restrict__ ei, int n, int g) {
    int i = blockIdx.x * blockDim.x + threadIdx.x;
    if (i == 0) {
        int allz = 1, anynz = 0;
        for (int k = 0; k < 256; k += 2) {
            if (ei[k + 1] != 0) allz = 0;
            if (ei[k]     != 0) anynz = 1;
        }
        g_is64 = (allz && anynz) ? 1 : 0;
    }
    if (i < n) { g_fill[i] = 0; g_odeg[i] = 0.f; }
    if (i < g * HD) g_pool[i] = 0.0f;
    if (i < g)      g_cnt[i]  = 0.0f;
    if (i < n * 8)  ((float4*)g_eagg)[i] = make_float4(0.f, 0.f, 0.f, 0.f);
}

// place each edge into its destination bucket (src only; 4B/edge);
// in-degree accumulates in g_fill; out-degree (float) for k_gemm_node.
__global__ void k_place(const void* __restrict__ ei, int E) {
    int is64 = g_is64;
    int e = blockIdx.x * blockDim.x + threadIdx.x;
    if (e < E) {
        int s, d;
        if (is64) {
            s = (int)((const long long*)ei)[e];
            d = (int)((const long long*)ei)[(long long)E + e];
        } else {
            s = ((const int*)ei)[e];
            d = ((const int*)ei)[E + e];
        }
        int slot = atomicAdd(&g_fill[d], 1);
        if (slot < CAP)
            g_bucket[(size_t)d * CAP + slot] = s;
        atomicAdd(&g_odeg[s], 1.0f);
    }
}

// dinv from fill counters (deg = fill + 1 self loop)
__global__ void k_dinv(int n) {
    int i = blockIdx.x * blockDim.x + threadIdx.x;
    if (i < n) g_dinv[i] = rsqrtf(1.0f + (float)g_fill[i]);
}

// eagg[src] += edge_attr[e]  (quarter-warp per edge pair: 8 lanes x float4;
// EA is a read-once 205MB stream -> __ldcs keeps it out of L2, leaving L2 to
// the RED-resident eagg)
__global__ void k_scatter_ea(const float* __restrict__ EA,
                             const void* __restrict__ ei, int E) {
    const int is64 = g_is64;
    const int lane = threadIdx.x & 7;
    int q  = (blockIdx.x * blockDim.x + threadIdx.x) >> 3;
    int nq = (gridDim.x * blockDim.x) >> 3;
    int e0 = q * 2;
    int stride = nq * 2;
    for (; e0 + 1 < E; e0 += stride) {
        int e1 = e0 + 1;
        int s0, s1;
        if (is64) {
            s0 = (int)((const long long*)ei)[e0];
            s1 = (int)((const long long*)ei)[e1];
        } else {
            s0 = ((const int*)ei)[e0];
            s1 = ((const int*)ei)[e1];
        }
        float4 v0 = __ldcs((const float4*)(EA + (size_t)e0 * 32) + lane);
        float4 v1 = __ldcs((const float4*)(EA + (size_t)e1 * 32) + lane);
        red_v4(g_eagg + (size_t)s0 * 32 + lane * 4, v0);
        red_v4(g_eagg + (size_t)s1 * 32 + lane * 4, v1);
    }
    if (e0 < E) {   // tail (odd E)
        int s = is64 ? (int)((const long long*)ei)[e0] : ((const int*)ei)[e0];
        float4 v = __ldcs((const float4*)(EA + (size_t)e0 * 32) + lane);
        red_v4(g_eagg + (size_t)s * 32 + lane * 4, v);
    }
}

// ---------------------------------------------------------------------------
// Fused node embed: out[r] = x[r]@Wn + eagg[r]@We + bn + odeg[r]*be
// Thread-per-row; W chunk in smem (uniform broadcast LDS.128); A tiles staged
// in smem pad-33 (conflict-free). x is read-once -> __ldcs.
// ---------------------------------------------------------------------------
__global__ __launch_bounds__(256)
void k_gemm_node(const float* __restrict__ x, int n,
                 const float* __restrict__ Wn, const float* __restrict__ bn,
                 const float* __restrict__ We, const float* __restrict__ be,
                 float* __restrict__ out) {
    __shared__ float ws[32 * 64];
    __shared__ float as[256 * 33];
    const int tid = threadIdx.x;
    const int r0  = blockIdx.x * 256;
    const int r   = r0 + tid;

    float4 acc[16];
    #pragma unroll
    for (int j = 0; j < 16; j++) acc[j] = make_float4(0.f, 0.f, 0.f, 0.f);

    // phase 1: x @ Wn   (K = 128, 4 chunks)
    for (int kc = 0; kc < 128; kc += 32) {
        __syncthreads();
        #pragma unroll
        for (int i = tid; i < 512; i += 256)
            ((float4*)ws)[i] = ((const float4*)Wn)[kc * 16 + i];
        #pragma unroll
        for (int q = 0; q < 8; q++) {
            int f = tid + 256 * q;
            int row = f >> 3, c4 = f & 7;
            int gr = r0 + row;
            float4 v = make_float4(0.f, 0.f, 0.f, 0.f);
            if (gr < n) v = __ldcs((const float4*)(x + (size_t)gr * 128 + kc) + c4);
            float* dst = &as[row * 33 + c4 * 4];
            dst[0] = v.x; dst[1] = v.y; dst[2] = v.z; dst[3] = v.w;
        }
        __syncthreads();
        #pragma unroll 8
        for (int k = 0; k < 32; k++) {
            float a = as[tid * 33 + k];
            const float4* w4 = (const float4*)(ws + k * 64);
            #pragma unroll
            for (int j = 0; j < 16; j++) {
                float4 w = w4[j];
                acc[j].x += a * w.x; acc[j].y += a * w.y;
                acc[j].z += a * w.z; acc[j].w += a * w.w;
            }
        }
    }

    // phase 2: eagg @ We   (K = 32, 1 chunk)
    __syncthreads();
    #pragma unroll
    for (int i = tid; i < 512; i += 256)
        ((float4*)ws)[i] = ((const float4*)We)[i];
    #pragma unroll
    for (int q = 0; q < 8; q++) {
        int f = tid + 256 * q;
        int row = f >> 3, c4 = f & 7;
        int gr = r0 + row;
        float4 v = make_float4(0.f, 0.f, 0.f, 0.f);
        if (gr < n) v = *(const float4*)(g_eagg + (size_t)gr * 32 + c4 * 4);
        float* dst = &as[row * 33 + c4 * 4];
        dst[0] = v.x; dst[1] = v.y; dst[2] = v.z; dst[3] = v.w;
    }
    __syncthreads();
    #pragma unroll 8
    for (int k = 0; k < 32; k++) {
        float a = as[tid * 33 + k];
        const float4* w4 = (const float4*)(ws + k * 64);
        #pragma unroll
        for (int j = 0; j < 16; j++) {
            float4 w = w4[j];
            acc[j].x += a * w.x; acc[j].y += a * w.y;
            acc[j].z += a * w.z; acc[j].w += a * w.w;
        }
    }

    if (r < n) {
        float od = g_odeg[r];
        float4* o = (float4*)(out + (size_t)r * HD);
        #pragma unroll
        for (int j = 0; j < 16; j++) {
            float4 b  = ((const float4*)bn)[j];
            float4 eb = ((const float4*)be)[j];
            float4 v;
            v.x = acc[j].x + b.x + od * eb.x;
            v.y = acc[j].y + b.y + od * eb.y;
            v.z = acc[j].z + b.z + od * eb.z;
            v.w = acc[j].w + b.w + od * eb.w;
            o[j] = v;
        }
    }
}

// ---------------------------------------------------------------------------
// Layer GEMM: acc = (RELU? relu(A[r,:]) : A[r,:]) @ W   (K=64)
// Writes ONLY t'[r] = acc * dinv[r]  (pre-scaled for the gather; the self-loop
// + bias seed is folded into k_gather since self term = dinv[r]*t'[r]).
// ---------------------------------------------------------------------------
template<bool RELU>
__global__ __launch_bounds__(256)
void k_gemm(const float* __restrict__ A, int n,
            const float* __restrict__ W,
            float* __restrict__ out) {
    __shared__ float ws[32 * 64];
    __shared__ float as[256 * 33];
    const int tid = threadIdx.x;
    const int r0  = blockIdx.x * 256;
    const int r   = r0 + tid;

    float4 acc[16];
    #pragma unroll
    for (int j = 0; j < 16; j++) acc[j] = make_float4(0.f, 0.f, 0.f, 0.f);

    for (int kc = 0; kc < 64; kc += 32) {
        __syncthreads();
        #pragma unroll
        for (int i = tid; i < 512; i += 256)
            ((float4*)ws)[i] = ((const float4*)W)[kc * 16 + i];
        #pragma unroll
        for (int q = 0; q < 8; q++) {
            int f = tid + 256 * q;
            int row = f >> 3, c4 = f & 7;
            int gr = r0 + row;
            float4 v = make_float4(0.f, 0.f, 0.f, 0.f);
            if (gr < n) v = *(const float4*)(A + (size_t)gr * 64 + kc + c4 * 4);
            if (RELU) {
                v.x = fmaxf(v.x, 0.f); v.y = fmaxf(v.y, 0.f);
                v.z = fmaxf(v.z, 0.f); v.w = fmaxf(v.w, 0.f);
            }
            float* dst = &as[row * 33 + c4 * 4];
            dst[0] = v.x; dst[1] = v.y; dst[2] = v.z; dst[3] = v.w;
        }
        __syncthreads();
        #pragma unroll 8
        for (int k = 0; k < 32; k++) {
            float a = as[tid * 33 + k];
            const float4* w4 = (const float4*)(ws + k * 64);
            #pragma unroll
            for (int j = 0; j < 16; j++) {
                float4 w = w4[j];
                acc[j].x += a * w.x; acc[j].y += a * w.y;
                acc[j].z += a * w.z; acc[j].w += a * w.w;
            }
        }
    }
    if (r < n) {
        float4* o = (float4*)(out + (size_t)r * HD);
        float di = g_dinv[r];
        #pragma unroll
        for (int j = 0; j < 16; j++) {
            float4 ts;
            ts.x = acc[j].x * di; ts.y = acc[j].y * di;
            ts.z = acc[j].z * di; ts.w = acc[j].w * di;
            o[j] = ts;
        }
    }
}

// ---------------------------------------------------------------------------
// Gather aggregation: warp per node n; computes the COMPLETE layer output:
//   out[n] = bias + dinv[n] * ( t'[n] + sum over in-edges t'[src] )
// float2 lane layout (lane owns elems 2l, 2l+1): 1 LDG.64 per row per lane
// (halves request count vs 2x LDG.32). Pure store, no atomics.
// ---------------------------------------------------------------------------
__global__ __launch_bounds__(256)
void k_gather(const float* __restrict__ t, const float* __restrict__ bias,
              float* __restrict__ out, int N) {
    int warp = (blockIdx.x * blockDim.x + threadIdx.x) >> 5;
    int lane = threadIdx.x & 31;
    if (warp >= N) return;
    int deg = g_fill[warp];
    if (deg > CAP) deg = CAP;
    const int* bk = &g_bucket[(size_t)warp * CAP];
    float dn = g_dinv[warp];
    // self term
    float2 a = ((const float2*)(t + (size_t)warp * HD))[lane];
    int i = 0;
    for (; i + 4 <= deg; i += 4) {
        int4 q = *(const int4*)(bk + i);        // broadcast LDG.128: 4 src idx
        float2 v0 = ((const float2*)(t + (size_t)q.x * HD))[lane];
        float2 v1 = ((const float2*)(t + (size_t)q.y * HD))[lane];
        float2 v2 = ((const float2*)(t + (size_t)q.z * HD))[lane];
        float2 v3 = ((const float2*)(t + (size_t)q.w * HD))[lane];
        a.x += (v0.x + v1.x) + (v2.x + v3.x);
        a.y += (v0.y + v1.y) + (v2.y + v3.y);
    }
    for (; i < deg; i++) {
        float2 v = ((const float2*)(t + (size_t)bk[i] * HD))[lane];
        a.x += v.x;
        a.y += v.y;
    }
    float2 b = ((const float2*)bias)[lane];
    float2 o;
    o.x = b.x + dn * a.x;
    o.y = b.y + dn * a.y;
    ((float2*)(out + (size_t)warp * HD))[lane] = o;
}

// sorted-batch mean-pool: warp per contiguous node chunk, register accumulate,
// flush on graph-id boundary.
__global__ void k_pool(const void* __restrict__ batch,
                       const float* __restrict__ h, int N) {
    const int is64 = g_is64;
    const int lane = threadIdx.x & 31;
    int warp = (blockIdx.x * blockDim.x + threadIdx.x) >> 5;
    int nw   = (gridDim.x * blockDim.x) >> 5;
    int chunk = (N + nw - 1) / nw;
    int n0 = warp * chunk;
    int n1 = min(N, n0 + chunk);
    float a0 = 0.f, a1 = 0.f, c = 0.f;
    int cur = -1;
    for (int n = n0; n < n1; n++) {
        int b = is64 ? (int)((const long long*)batch)[n] : ((const int*)batch)[n];
        if (b != cur) {
            if (cur >= 0) {
                atomicAdd(&g_pool[cur * HD + 2 * lane],     a0);
                atomicAdd(&g_pool[cur * HD + 2 * lane + 1], a1);
                if (lane == 0) atomicAdd(&g_cnt[cur], c);
            }
            cur = b; a0 = a1 = 0.f; c = 0.f;
        }
        float2 v = ((const float2*)(h + (size_t)n * HD))[lane];
        a0 += v.x;
        a1 += v.y;
        c  += 1.0f;
    }
    if (cur >= 0) {
        atomicAdd(&g_pool[cur * HD + 2 * lane],     a0);
        atomicAdd(&g_pool[cur * HD + 2 * lane + 1], a1);
        if (lane == 0) atomicAdd(&g_cnt[cur], c);
    }
}

// warp-per-graph classifier: relu(mean @ Wc1 + bc1) @ Wc2 + bc2
__global__ void k_classify(const float* __restrict__ Wc1, const float* __restrict__ bc1,
                           const float* __restrict__ Wc2, const float* __restrict__ bc2,
                           float* __restrict__ out, int G) {
    int warp = (blockIdx.x * blockDim.x + threadIdx.x) >> 5;
    int lane = threadIdx.x & 31;
    if (warp >= G) return;
    float inv = 1.0f / fmaxf(g_cnt[warp], 1.0f);
    float c1 = bc1[lane];
    #pragma unroll 8
    for (int k = 0; k < HD; k++) {
        float m = g_pool[warp * HD + k] * inv;
        c1 += m * Wc1[k * 32 + lane];
    }
    c1 = fmaxf(c1, 0.f);
    float v = c1 * Wc2[lane];
    #pragma unroll
    for (int off = 16; off; off >>= 1)
        v += __shfl_down_sync(0xffffffffu, v, off);
    if (lane == 0) out[warp] = v + bc2[0];
}

static inline int cdiv(int a, int b) { return (a + b - 1) / b; }

extern "C" void kernel_launch(void* const* d_in, const int* in_sizes, int n_in,
                              void* d_out, int out_size) {
    const float* x     = (const float*)d_in[0];
    const void*  ei    = d_in[1];
    const float* ea    = (const float*)d_in[2];
    const void*  batch = d_in[3];
    const float* Wn  = (const float*)d_in[4];  const float* bn  = (const float*)d_in[5];
    const float* We  = (const float*)d_in[6];  const float* be  = (const float*)d_in[7];
    const float* W1  = (const float*)d_in[8];  const float* b1  = (const float*)d_in[9];
    const float* W2  = (const float*)d_in[10]; const float* b2  = (const float*)d_in[11];
    const float* W3  = (const float*)d_in[12]; const float* b3  = (const float*)d_in[13];
    const float* Wc1 = (const float*)d_in[14]; const float* bc1 = (const float*)d_in[15];
    const float* Wc2 = (const float*)d_in[16]; const float* bc2 = (const float*)d_in[17];
    float* out = (float*)d_out;

    const int N = in_sizes[3];        // batch has N elements
    const int E = in_sizes[2] / 32;   // edge_attr is [E,32]
    const int G = out_size;

    float *ph, *ph2, *pt;
    cudaGetSymbolAddress((void**)&ph,  g_h);
    cudaGetSymbolAddress((void**)&ph2, g_h2);
    cudaGetSymbolAddress((void**)&pt,  g_t);

    // setup covers max(N, G*HD, N*8) threads
    int setupN = N * 8;
    if (G * HD > setupN) setupN = G * HD;
    k_setup<<<cdiv(setupN, 256), 256>>>((const int*)ei, N, G);
    k_place<<<cdiv(E, 256), 256>>>(ei, E);
    k_dinv <<<cdiv(N, 256), 256>>>(N);
    k_scatter_ea<<<2048, 256>>>(ea, ei, E);

    // fused node embed: x@Wn + eagg@We + bn + odeg*be
    k_gemm_node<<<cdiv(N, 256), 256>>>(x, N, Wn, bn, We, be, ph);

    const int gw = cdiv(N * 32, 256);   // gather: warp per node

    // GCN layer 1 (no relu on input)
    k_gemm<false><<<cdiv(N, 256), 256>>>(ph, N, W1, pt);
    k_gather<<<gw, 256>>>(pt, b1, ph2, N);

    // GCN layer 2 (relu on input)
    k_gemm<true><<<cdiv(N, 256), 256>>>(ph2, N, W2, pt);
    k_gather<<<gw, 256>>>(pt, b2, ph, N);

    // GCN layer 3 (relu on input)
    k_gemm<true><<<cdiv(N, 256), 256>>>(ph, N, W3, pt);
    k_gather<<<gw, 256>>>(pt, b3, ph2, N);

    // pool + classify
    k_pool<<<64, 256>>>(batch, ph2, N);
    k_classify<<<cdiv(G * 32, 256), 256>>>(Wc1, bc1, Wc2, bc2, out, G);
}